// round 5
// baseline (speedup 1.0000x reference)
#include <cuda_runtime.h>
#include <float.h>

#define MAXN 100000
#define GRIDMAX (128*128*128)
#define FLAGMAX (64*64*64)

// ---------------- static device scratch (no allocations allowed) ----------------
__device__ int   g_gridA[GRIDMAX];
__device__ int   g_gridB[GRIDMAX];
__device__ int   g_flags[FLAGMAX];
__device__ int   g_ranks[FLAGMAX];
__device__ int   g_bsums[1024];
__device__ int   g_pairs[27 * MAXN];
__device__ int   g_coordsA[MAXN * 3];
__device__ int   g_coordsB[MAXN * 3];
__device__ float g_featsA[MAXN * 256];
__device__ float g_featsB[MAXN * 256];
__device__ int   g_counts[8];

// ---------------- small utility kernels ----------------
__global__ void k_fill(int* a, int nelem, int val) {
    int i = blockIdx.x * blockDim.x + threadIdx.x;
    if (i < nelem) a[i] = val;
}

__global__ void k_set(int* p, int v) { *p = v; }

__global__ void k_init0(const int* __restrict__ coors, int n,
                        int* __restrict__ grid, int* __restrict__ coords) {
    int i = blockIdx.x * blockDim.x + threadIdx.x;
    if (i >= n) return;
    int z = coors[i * 4 + 1];
    int y = coors[i * 4 + 2];
    int x = coors[i * 4 + 3];
    coords[i * 3 + 0] = z;
    coords[i * 3 + 1] = y;
    coords[i * 3 + 2] = x;
    grid[(z * 128 + y) * 128 + x] = i;
}

// Build 27-neighbor pair table for current level.
__global__ void k_pairs(const int* __restrict__ coords, const int* __restrict__ grid,
                        const int* __restrict__ cnt, int S, int* __restrict__ pairs) {
    int i = blockIdx.x * blockDim.x + threadIdx.x;
    int n = *cnt;
    if (i >= n) return;
    int z = coords[i * 3 + 0];
    int y = coords[i * 3 + 1];
    int x = coords[i * 3 + 2];
#pragma unroll
    for (int k = 0; k < 27; k++) {
        int dz = k / 9 - 1;
        int dy = (k / 3) % 3 - 1;
        int dx = k % 3 - 1;
        int zz = z + dz, yy = y + dy, xx = x + dx;
        int v = -1;
        if (zz >= 0 && zz < S && yy >= 0 && yy < S && xx >= 0 && xx < S)
            v = grid[(zz * S + yy) * S + xx];
        pairs[k * MAXN + i] = v;
    }
}

// ---------------- gather-GEMM submanifold conv ----------------
// out[n, Cout] = sum_k gather(fin, pairs[k]) @ W[k]   (W: [27, Cin, Cout])
// Tile: 64 rows x 64 cols, BK=16, 256 threads, 4x4 per-thread micro tile.
// Dead taps (no active neighbor in the whole 64-row block) are skipped.
__global__ __launch_bounds__(256) void k_conv(
    const float* __restrict__ fin, const float* __restrict__ W,
    const int* __restrict__ pairs, const int* __restrict__ cnt,
    float* __restrict__ fout, int Cin, int Cout) {
    int n = *cnt;
    int rowBase = blockIdx.x * 64;
    if (rowBase >= n) return;
    int colBase = blockIdx.y * 64;

    int tid = threadIdx.x;
    int tx = tid & 15;   // 0..15 -> cols tx*4..tx*4+3
    int ty = tid >> 4;   // 0..15 -> rows ty*4..ty*4+3

    __shared__ float As[16][64];   // [ci][row]  (transposed)
    __shared__ float Bs[16][64];   // [ci][col]
    __shared__ int   sIdx[64];

    float acc[4][4];
#pragma unroll
    for (int i = 0; i < 4; i++)
#pragma unroll
        for (int j = 0; j < 4; j++) acc[i][j] = 0.f;

    int lrow = tid >> 2;        // 0..63
    int lc   = (tid & 3) * 4;   // 0,4,8,12
    int bkk  = tid >> 4;        // 0..15
    int bcb  = (tid & 15) * 4;  // 0..60

    for (int k = 0; k < 27; k++) {
        int myIdx = -1;
        if (tid < 64) {
            int r = rowBase + tid;
            myIdx = (r < n) ? pairs[k * MAXN + r] : -1;
            sIdx[tid] = myIdx;
        }
        // Barrier: makes sIdx visible AND protects previous iteration's
        // smem reads (all sIdx/As/Bs reads happen before the fill-barrier
        // of the prior ck iteration, so no WAR hazard here).
        int active = __syncthreads_or(myIdx >= 0);
        if (!active) continue;   // uniform across block

        const float* wk = W + (size_t)k * Cin * Cout;
        for (int ck = 0; ck < Cin; ck += 16) {
            __syncthreads();   // WAR protection on As/Bs vs previous FMA phase
            int idx = sIdx[lrow];
            if (Cin >= 16) {
                // Cin is a multiple of 16 here -> no per-element bounds check
                float4 v = make_float4(0.f, 0.f, 0.f, 0.f);
                if (idx >= 0)
                    v = *reinterpret_cast<const float4*>(fin + (size_t)idx * Cin + ck + lc);
                As[lc + 0][lrow] = v.x;
                As[lc + 1][lrow] = v.y;
                As[lc + 2][lrow] = v.z;
                As[lc + 3][lrow] = v.w;
            } else {
#pragma unroll
                for (int q = 0; q < 4; q++) {
                    int c = lc + q;
                    float v = 0.f;
                    if (idx >= 0 && (ck + c) < Cin) v = fin[(size_t)idx * Cin + ck + c];
                    As[c][lrow] = v;
                }
            }
            {
                int kr = ck + bkk;
                int ccg = colBase + bcb;
                float4 b = make_float4(0.f, 0.f, 0.f, 0.f);
                if (kr < Cin && ccg < Cout)   // Cout%4==0, ccg%4==0 -> whole float4 in-bounds
                    b = *reinterpret_cast<const float4*>(wk + (size_t)kr * Cout + ccg);
                *reinterpret_cast<float4*>(&Bs[bkk][bcb]) = b;
            }
            __syncthreads();
#pragma unroll
            for (int kk = 0; kk < 16; kk++) {
                float a[4], b[4];
#pragma unroll
                for (int i = 0; i < 4; i++) a[i] = As[kk][ty * 4 + i];
#pragma unroll
                for (int j = 0; j < 4; j++) b[j] = Bs[kk][tx * 4 + j];
#pragma unroll
                for (int i = 0; i < 4; i++)
#pragma unroll
                    for (int j = 0; j < 4; j++) acc[i][j] += a[i] * b[j];
            }
        }
    }

#pragma unroll
    for (int i = 0; i < 4; i++) {
        int r = rowBase + ty * 4 + i;
        if (r >= n) continue;
        int c = colBase + tx * 4;
        if (c < Cout) {  // Cout%4==0 -> whole float4 in-bounds
            float4 o = make_float4(acc[i][0], acc[i][1], acc[i][2], acc[i][3]);
            *reinterpret_cast<float4*>(fout + (size_t)r * Cout + c) = o;
        }
    }
}

// ---------------- pooling structure (sorted unique via dense scan) ----------------
__global__ void k_mark(const int* __restrict__ coords, const int* __restrict__ cnt,
                       int S2, int* __restrict__ flags) {
    int i = blockIdx.x * blockDim.x + threadIdx.x;
    if (i >= *cnt) return;
    int z = coords[i * 3 + 0] >> 1;
    int y = coords[i * 3 + 1] >> 1;
    int x = coords[i * 3 + 2] >> 1;
    flags[(z * S2 + y) * S2 + x] = 1;
}

__global__ void k_scan_block(const int* __restrict__ flags, int* __restrict__ ranks,
                             int* __restrict__ bsums, int D) {
    __shared__ int s[1024];
    int tid = threadIdx.x;
    int i = blockIdx.x * 1024 + tid;
    int v = (i < D) ? flags[i] : 0;
    s[tid] = v;
    __syncthreads();
    for (int off = 1; off < 1024; off <<= 1) {
        int t = (tid >= off) ? s[tid - off] : 0;
        __syncthreads();
        s[tid] += t;
        __syncthreads();
    }
    if (i < D) ranks[i] = s[tid] - v;    // exclusive
    if (tid == 1023) bsums[blockIdx.x] = s[1023];
}

__global__ void k_scan_sums(int* __restrict__ bsums, int nB) {
    __shared__ int s[1024];
    int tid = threadIdx.x;
    int v = (tid < nB) ? bsums[tid] : 0;
    s[tid] = v;
    __syncthreads();
    for (int off = 1; off < 1024; off <<= 1) {
        int t = (tid >= off) ? s[tid - off] : 0;
        __syncthreads();
        s[tid] += t;
        __syncthreads();
    }
    if (tid < nB) bsums[tid] = s[tid] - v;  // exclusive
}

__global__ void k_scan_add(int* __restrict__ ranks, const int* __restrict__ flags,
                           const int* __restrict__ bsums, int D, int* __restrict__ cntOut) {
    int i = blockIdx.x * 1024 + threadIdx.x;
    if (i < D) {
        ranks[i] += bsums[blockIdx.x];
        if (i == D - 1) *cntOut = ranks[i] + flags[i];
    }
}

__global__ void k_build(const int* __restrict__ flags, const int* __restrict__ ranks,
                        int S2, int* __restrict__ gridN, int* __restrict__ coordsN) {
    int c = blockIdx.x * blockDim.x + threadIdx.x;
    int D = S2 * S2 * S2;
    if (c >= D) return;
    int f = flags[c];
    int r = ranks[c];
    gridN[c] = f ? r : -1;
    if (f) {
        int z = c / (S2 * S2);
        int rem = c % (S2 * S2);
        coordsN[r * 3 + 0] = z;
        coordsN[r * 3 + 1] = rem / S2;
        coordsN[r * 3 + 2] = rem % S2;
    }
}

// Gather-max over the <=8 children of each coarse voxel (every segment non-empty).
__global__ void k_pool(const float* __restrict__ fin, float* __restrict__ fout,
                       const int* __restrict__ gridC, const int* __restrict__ coordsN,
                       const int* __restrict__ cntN, int S, int C) {
    int gid = blockIdx.x * blockDim.x + threadIdx.x;
    int j = gid / C;
    int ch = gid % C;
    if (j >= *cntN) return;
    int z = coordsN[j * 3 + 0] * 2;
    int y = coordsN[j * 3 + 1] * 2;
    int x = coordsN[j * 3 + 2] * 2;
    float m = -FLT_MAX;
#pragma unroll
    for (int d = 0; d < 8; d++) {
        int zz = z + (d >> 2);
        int yy = y + ((d >> 1) & 1);
        int xx = x + (d & 1);
        int idx = gridC[(zz * S + yy) * S + xx];
        if (idx >= 0) m = fmaxf(m, fin[idx * C + ch]);
    }
    fout[j * C + ch] = m;
}

// ---------------- host orchestration ----------------
extern "C" void kernel_launch(void* const* d_in, const int* in_sizes, int n_in,
                              void* d_out, int out_size) {
    const float* features = (const float*)d_in[0];
    const int*   coors    = (const int*)d_in[1];
    const float* W[14];
    for (int i = 0; i < 14; i++) W[i] = (const float*)d_in[3 + i];
    float* dout = (float*)d_out;
    int n0 = in_sizes[0] / 3;

    int *gridA, *gridB, *flags, *ranks, *bsums, *pairs, *coordsA, *coordsB, *counts;
    float *featsA, *featsB;
    cudaGetSymbolAddress((void**)&gridA, g_gridA);
    cudaGetSymbolAddress((void**)&gridB, g_gridB);
    cudaGetSymbolAddress((void**)&flags, g_flags);
    cudaGetSymbolAddress((void**)&ranks, g_ranks);
    cudaGetSymbolAddress((void**)&bsums, g_bsums);
    cudaGetSymbolAddress((void**)&pairs, g_pairs);
    cudaGetSymbolAddress((void**)&coordsA, g_coordsA);
    cudaGetSymbolAddress((void**)&coordsB, g_coordsB);
    cudaGetSymbolAddress((void**)&featsA, g_featsA);
    cudaGetSymbolAddress((void**)&featsB, g_featsB);
    cudaGetSymbolAddress((void**)&counts, g_counts);

    // level 0 structure from input coords
    k_fill<<<(GRIDMAX + 1023) / 1024, 1024>>>(gridA, GRIDMAX, -1);
    k_init0<<<(n0 + 255) / 256, 256>>>(coors, n0, gridA, coordsA);
    k_set<<<1, 1>>>(counts, n0);

    const int S[7] = {128, 64, 32, 16, 8, 4, 2};
    const int M[7] = {100000, 100000, 32768, 4096, 512, 64, 8};
    const int CH[7][3] = {{3, 64, 64},    {64, 96, 96},   {96, 128, 128},
                          {128, 160, 160}, {160, 192, 192}, {192, 224, 224},
                          {224, 256, 256}};

    int* gc = gridA; int* gn = gridB;
    int* cc = coordsA; int* cn = coordsB;
    const float* cur = features;

    for (int L = 0; L < 7; L++) {
        int s = S[L], m = M[L];
        int Cin = CH[L][0], Cmid = CH[L][1], Cout = CH[L][2];

        k_pairs<<<(m + 255) / 256, 256>>>(cc, gc, counts + L, s, pairs);

        float* o1 = (cur == featsA) ? featsB : featsA;
        {
            dim3 g((m + 63) / 64, (Cmid + 63) / 64);
            k_conv<<<g, 256>>>(cur, W[2 * L], pairs, counts + L, o1, Cin, Cmid);
        }
        float* o2 = (L == 6) ? dout : ((o1 == featsA) ? featsB : featsA);
        {
            dim3 g((m + 63) / 64, (Cout + 63) / 64);
            k_conv<<<g, 256>>>(o1, W[2 * L + 1], pairs, counts + L, o2, Cmid, Cout);
        }

        if (L < 6) {
            int s2 = s / 2;
            int D2 = s2 * s2 * s2;
            int m2 = M[L + 1];
            k_fill<<<(D2 + 1023) / 1024, 1024>>>(flags, D2, 0);
            k_mark<<<(m + 255) / 256, 256>>>(cc, counts + L, s2, flags);
            int nB = (D2 + 1023) / 1024;
            k_scan_block<<<nB, 1024>>>(flags, ranks, bsums, D2);
            k_scan_sums<<<1, 1024>>>(bsums, nB);
            k_scan_add<<<nB, 1024>>>(ranks, flags, bsums, D2, counts + L + 1);
            k_build<<<(D2 + 255) / 256, 256>>>(flags, ranks, s2, gn, cn);

            float* po = (o2 == featsA) ? featsB : featsA;
            long tot = (long)m2 * Cout;
            k_pool<<<(int)((tot + 255) / 256), 256>>>(o2, po, gc, cn, counts + L + 1, s, Cout);
            cur = po;

            int* t = gc; gc = gn; gn = t;
            t = cc; cc = cn; cn = t;
        }
    }
}

// round 11
// speedup vs baseline: 1.0500x; 1.0500x over previous
#include <cuda_runtime.h>
#include <float.h>
#include <stdint.h>

#define MAXN 100000
#define GRIDMAX (128*128*128)
#define FLAGMAX (64*64*64)

#define BM 128
#define BN 64
#define BK 16
#define LDA (BK + 4)   // 20 floats per row: pad -> ldmatrix-friendly, 80B row stride (16B aligned)

// ---------------- static device scratch (no allocations allowed) ----------------
__device__ int   g_gridA[GRIDMAX];
__device__ int   g_gridB[GRIDMAX];
__device__ int   g_flags[FLAGMAX];
__device__ int   g_ranks[FLAGMAX];
__device__ int   g_bsums[1024];
__device__ int   g_pairs[27 * MAXN];
__device__ int   g_coordsA[MAXN * 3];
__device__ int   g_coordsB[MAXN * 3];
__device__ float g_featsA[MAXN * 256];
__device__ float g_featsB[MAXN * 256];
__device__ int   g_counts[8];

// ---------------- small utility kernels ----------------
__global__ void k_fill(int* a, int nelem, int val) {
    int i = blockIdx.x * blockDim.x + threadIdx.x;
    if (i < nelem) a[i] = val;
}

__global__ void k_set(int* p, int v) { *p = v; }

__global__ void k_init0(const int* __restrict__ coors, int n,
                        int* __restrict__ grid, int* __restrict__ coords) {
    int i = blockIdx.x * blockDim.x + threadIdx.x;
    if (i >= n) return;
    int z = coors[i * 4 + 1];
    int y = coors[i * 4 + 2];
    int x = coors[i * 4 + 3];
    coords[i * 3 + 0] = z;
    coords[i * 3 + 1] = y;
    coords[i * 3 + 2] = x;
    grid[(z * 128 + y) * 128 + x] = i;
}

// Build 27-neighbor pair table for current level.
__global__ void k_pairs(const int* __restrict__ coords, const int* __restrict__ grid,
                        const int* __restrict__ cnt, int S, int* __restrict__ pairs) {
    int i = blockIdx.x * blockDim.x + threadIdx.x;
    int n = *cnt;
    if (i >= n) return;
    int z = coords[i * 3 + 0];
    int y = coords[i * 3 + 1];
    int x = coords[i * 3 + 2];
#pragma unroll
    for (int k = 0; k < 27; k++) {
        int dz = k / 9 - 1;
        int dy = (k / 3) % 3 - 1;
        int dx = k % 3 - 1;
        int zz = z + dz, yy = y + dy, xx = x + dx;
        int v = -1;
        if (zz >= 0 && zz < S && yy >= 0 && yy < S && xx >= 0 && xx < S)
            v = grid[(zz * S + yy) * S + xx];
        pairs[k * MAXN + i] = v;
    }
}

// ---------------- tf32 mma helpers ----------------
__device__ __forceinline__ uint32_t f2tf32(float x) {
    uint32_t r;
    asm("cvt.rna.tf32.f32 %0, %1;" : "=r"(r) : "f"(x));
    return r;
}

__device__ __forceinline__ void mma_tf32(float* c, const uint32_t* a, const uint32_t* b) {
    asm volatile("mma.sync.aligned.m16n8k8.row.col.f32.tf32.tf32.f32 "
        "{%0,%1,%2,%3}, {%4,%5,%6,%7}, {%8,%9}, {%0,%1,%2,%3};"
        : "+f"(c[0]), "+f"(c[1]), "+f"(c[2]), "+f"(c[3])
        : "r"(a[0]), "r"(a[1]), "r"(a[2]), "r"(a[3]), "r"(b[0]), "r"(b[1]));
}

__device__ __forceinline__ void ldsm4(uint32_t* r, const float* p) {
    uint32_t saddr = (uint32_t)__cvta_generic_to_shared(p);
    asm volatile("ldmatrix.sync.aligned.m8n8.x4.shared.b16 {%0,%1,%2,%3}, [%4];"
        : "=r"(r[0]), "=r"(r[1]), "=r"(r[2]), "=r"(r[3]) : "r"(saddr));
}

// ---------------- gather-GEMM submanifold conv via 3xTF32 tensor-core mma ----------------
// out[n, Cout] = sum_k gather(fin, pairs[k]) @ W[k]   (W: [27, Cin, Cout])
// Block tile 128x64, 8 warps (4x2), warp tile 32x32, BK=16 (2 x k8 steps).
// A and B are split hi/lo (tf32) at smem-fill; inner loop: ldmatrix + 3 mma per position.
__global__ __launch_bounds__(256) void k_conv_mma(
    const float* __restrict__ fin, const float* __restrict__ W,
    const int* __restrict__ pairs, const int* __restrict__ cnt,
    float* __restrict__ fout, int Cin, int Cout)
{
    int n = *cnt;
    int rowBase = blockIdx.x * BM;
    if (rowBase >= n) return;
    int colBase = blockIdx.y * BN;

    int tid = threadIdx.x;
    int lane = tid & 31;
    int wid = tid >> 5;
    int wm = wid & 3;          // 4 warps along M
    int wn = wid >> 2;         // 2 warps along N
    int mW = wm * 32;          // warp tile origin in block tile
    int nW = wn * 32;

    __shared__ __align__(16) float As[2][BM][LDA];   // [hi/lo][row][k]
    __shared__ __align__(16) float Bs[2][BN][LDA];   // [hi/lo][col][k]  (transposed weights)
    __shared__ int sIdx[BM];

    float acc[2][4][4];
#pragma unroll
    for (int a = 0; a < 2; a++)
#pragma unroll
        for (int b = 0; b < 4; b++)
#pragma unroll
            for (int c = 0; c < 4; c++) acc[a][b][c] = 0.f;

    // fill assignments
    int arow = tid >> 1;            // 0..127
    int acol = (tid & 1) * 8;       // 0 or 8
    int bk   = tid & 15;            // k within BK
    int bn4  = (tid >> 4) * 4;      // 4 consecutive n columns

    for (int k = 0; k < 27; k++) {
        int myIdx = -1;
        if (tid < BM) {
            int r = rowBase + tid;
            myIdx = (r < n) ? pairs[k * MAXN + r] : -1;
            sIdx[tid] = myIdx;
        }
        // uniform barrier: publishes sIdx, protects prior smem reads, skips dead taps
        int active = __syncthreads_or(myIdx >= 0);
        if (!active) continue;

        const float* wk = W + (size_t)k * Cin * Cout;

        for (int ck = 0; ck < Cin; ck += BK) {
            __syncthreads();   // WAR: previous kh-phase ldmatrix reads done
            // ---- A fill: 8 floats per thread, split hi/lo ----
            {
                int idx = sIdx[arow];
                float v[8];
                if (idx >= 0 && Cin >= BK) {
                    const float4* p = reinterpret_cast<const float4*>(
                        fin + (size_t)idx * Cin + ck + acol);
                    float4 v0 = p[0], v1 = p[1];
                    v[0] = v0.x; v[1] = v0.y; v[2] = v0.z; v[3] = v0.w;
                    v[4] = v1.x; v[5] = v1.y; v[6] = v1.z; v[7] = v1.w;
                } else {
#pragma unroll
                    for (int j = 0; j < 8; j++) {
                        int c = ck + acol + j;
                        v[j] = (idx >= 0 && c < Cin) ? fin[(size_t)idx * Cin + c] : 0.f;
                    }
                }
#pragma unroll
                for (int j = 0; j < 8; j++) {
                    uint32_t hb = f2tf32(v[j]);
                    float hf = __uint_as_float(hb);
                    uint32_t lb = f2tf32(v[j] - hf);
                    As[0][arow][acol + j] = hf;
                    As[1][arow][acol + j] = __uint_as_float(lb);
                }
            }
            // ---- B fill: 4 consecutive n per thread (float4 from W), transpose+split ----
            {
                int kk = ck + bk;
                int gc = colBase + bn4;
                float v[4];
                if (kk < Cin && gc < Cout) {   // gc%4==0, Cout%4==0 -> whole float4 in-bounds
                    float4 t4 = *reinterpret_cast<const float4*>(wk + (size_t)kk * Cout + gc);
                    v[0] = t4.x; v[1] = t4.y; v[2] = t4.z; v[3] = t4.w;
                } else {
                    v[0] = v[1] = v[2] = v[3] = 0.f;
                }
#pragma unroll
                for (int j = 0; j < 4; j++) {
                    uint32_t hb = f2tf32(v[j]);
                    float hf = __uint_as_float(hb);
                    uint32_t lb = f2tf32(v[j] - hf);
                    Bs[0][bn4 + j][bk] = hf;
                    Bs[1][bn4 + j][bk] = __uint_as_float(lb);
                }
            }
            __syncthreads();

#pragma unroll
            for (int kh = 0; kh < BK; kh += 8) {
                uint32_t ah[2][4], al[2][4], bh[2][4], bl[2][4];
                // A frags: lanes 0-7 rows+0..7@kh, 8-15 rows+8..15@kh,
                //          16-23 rows+0..7@kh+4, 24-31 rows+8..15@kh+4
#pragma unroll
                for (int mt = 0; mt < 2; mt++) {
                    int r = mW + mt * 16 + (lane & 15);
                    int c = kh + (lane >> 4) * 4;
                    ldsm4(ah[mt], &As[0][r][c]);
                    ldsm4(al[mt], &As[1][r][c]);
                }
                // B frags (pair of n8 tiles per x4):
                // lanes 0-7: n+0..7@kh, 8-15: n+0..7@kh+4, 16-23: n+8..15@kh, 24-31: n+8..15@kh+4
#pragma unroll
                for (int p = 0; p < 2; p++) {
                    int r = nW + p * 16 + ((lane >> 4) * 8) + (lane & 7);
                    int c = kh + ((lane >> 3) & 1) * 4;
                    ldsm4(bh[p], &Bs[0][r][c]);
                    ldsm4(bl[p], &Bs[1][r][c]);
                }
                // bh[p] = {b0(n=2p), b1(n=2p), b0(n=2p+1), b1(n=2p+1)}
#pragma unroll
                for (int mt = 0; mt < 2; mt++)
#pragma unroll
                    for (int nt = 0; nt < 4; nt++) {
                        const uint32_t* bhp = &bh[nt >> 1][(nt & 1) * 2];
                        const uint32_t* blp = &bl[nt >> 1][(nt & 1) * 2];
                        mma_tf32(acc[mt][nt], al[mt], bhp);
                        mma_tf32(acc[mt][nt], ah[mt], blp);
                        mma_tf32(acc[mt][nt], ah[mt], bhp);
                    }
            }
        }
    }

    // ---- epilogue ----
    int g = lane >> 2, tig = lane & 3;
#pragma unroll
    for (int mt = 0; mt < 2; mt++) {
#pragma unroll
        for (int nt = 0; nt < 4; nt++) {
            int col = colBase + nW + nt * 8 + tig * 2;
            if (col >= Cout) continue;   // Cout even, col even -> float2 fully in-bounds
            int r0 = rowBase + mW + mt * 16 + g;
            if (r0 < n) {
                float2 o = make_float2(acc[mt][nt][0], acc[mt][nt][1]);
                *reinterpret_cast<float2*>(fout + (size_t)r0 * Cout + col) = o;
            }
            int r1 = r0 + 8;
            if (r1 < n) {
                float2 o = make_float2(acc[mt][nt][2], acc[mt][nt][3]);
                *reinterpret_cast<float2*>(fout + (size_t)r1 * Cout + col) = o;
            }
        }
    }
}

// ---------------- pooling structure (sorted unique via dense scan) ----------------
__global__ void k_mark(const int* __restrict__ coords, const int* __restrict__ cnt,
                       int S2, int* __restrict__ flags) {
    int i = blockIdx.x * blockDim.x + threadIdx.x;
    if (i >= *cnt) return;
    int z = coords[i * 3 + 0] >> 1;
    int y = coords[i * 3 + 1] >> 1;
    int x = coords[i * 3 + 2] >> 1;
    flags[(z * S2 + y) * S2 + x] = 1;
}

__global__ void k_scan_block(const int* __restrict__ flags, int* __restrict__ ranks,
                             int* __restrict__ bsums, int D) {
    __shared__ int s[1024];
    int tid = threadIdx.x;
    int i = blockIdx.x * 1024 + tid;
    int v = (i < D) ? flags[i] : 0;
    s[tid] = v;
    __syncthreads();
    for (int off = 1; off < 1024; off <<= 1) {
        int t = (tid >= off) ? s[tid - off] : 0;
        __syncthreads();
        s[tid] += t;
        __syncthreads();
    }
    if (i < D) ranks[i] = s[tid] - v;    // exclusive
    if (tid == 1023) bsums[blockIdx.x] = s[1023];
}

__global__ void k_scan_sums(int* __restrict__ bsums, int nB) {
    __shared__ int s[1024];
    int tid = threadIdx.x;
    int v = (tid < nB) ? bsums[tid] : 0;
    s[tid] = v;
    __syncthreads();
    for (int off = 1; off < 1024; off <<= 1) {
        int t = (tid >= off) ? s[tid - off] : 0;
        __syncthreads();
        s[tid] += t;
        __syncthreads();
    }
    if (tid < nB) bsums[tid] = s[tid] - v;  // exclusive
}

__global__ void k_scan_add(int* __restrict__ ranks, const int* __restrict__ flags,
                           const int* __restrict__ bsums, int D, int* __restrict__ cntOut) {
    int i = blockIdx.x * 1024 + threadIdx.x;
    if (i < D) {
        ranks[i] += bsums[blockIdx.x];
        if (i == D - 1) *cntOut = ranks[i] + flags[i];
    }
}

__global__ void k_build(const int* __restrict__ flags, const int* __restrict__ ranks,
                        int S2, int* __restrict__ gridN, int* __restrict__ coordsN) {
    int c = blockIdx.x * blockDim.x + threadIdx.x;
    int D = S2 * S2 * S2;
    if (c >= D) return;
    int f = flags[c];
    int r = ranks[c];
    gridN[c] = f ? r : -1;
    if (f) {
        int z = c / (S2 * S2);
        int rem = c % (S2 * S2);
        coordsN[r * 3 + 0] = z;
        coordsN[r * 3 + 1] = rem / S2;
        coordsN[r * 3 + 2] = rem % S2;
    }
}

// Gather-max over the <=8 children of each coarse voxel (every segment non-empty).
__global__ void k_pool(const float* __restrict__ fin, float* __restrict__ fout,
                       const int* __restrict__ gridC, const int* __restrict__ coordsN,
                       const int* __restrict__ cntN, int S, int C) {
    int gid = blockIdx.x * blockDim.x + threadIdx.x;
    int j = gid / C;
    int ch = gid % C;
    if (j >= *cntN) return;
    int z = coordsN[j * 3 + 0] * 2;
    int y = coordsN[j * 3 + 1] * 2;
    int x = coordsN[j * 3 + 2] * 2;
    float m = -FLT_MAX;
#pragma unroll
    for (int d = 0; d < 8; d++) {
        int zz = z + (d >> 2);
        int yy = y + ((d >> 1) & 1);
        int xx = x + (d & 1);
        int idx = gridC[(zz * S + yy) * S + xx];
        if (idx >= 0) m = fmaxf(m, fin[idx * C + ch]);
    }
    fout[j * C + ch] = m;
}

// ---------------- host orchestration ----------------
extern "C" void kernel_launch(void* const* d_in, const int* in_sizes, int n_in,
                              void* d_out, int out_size) {
    const float* features = (const float*)d_in[0];
    const int*   coors    = (const int*)d_in[1];
    const float* W[14];
    for (int i = 0; i < 14; i++) W[i] = (const float*)d_in[3 + i];
    float* dout = (float*)d_out;
    int n0 = in_sizes[0] / 3;

    int *gridA, *gridB, *flags, *ranks, *bsums, *pairs, *coordsA, *coordsB, *counts;
    float *featsA, *featsB;
    cudaGetSymbolAddress((void**)&gridA, g_gridA);
    cudaGetSymbolAddress((void**)&gridB, g_gridB);
    cudaGetSymbolAddress((void**)&flags, g_flags);
    cudaGetSymbolAddress((void**)&ranks, g_ranks);
    cudaGetSymbolAddress((void**)&bsums, g_bsums);
    cudaGetSymbolAddress((void**)&pairs, g_pairs);
    cudaGetSymbolAddress((void**)&coordsA, g_coordsA);
    cudaGetSymbolAddress((void**)&coordsB, g_coordsB);
    cudaGetSymbolAddress((void**)&featsA, g_featsA);
    cudaGetSymbolAddress((void**)&featsB, g_featsB);
    cudaGetSymbolAddress((void**)&counts, g_counts);

    // level 0 structure from input coords
    k_fill<<<(GRIDMAX + 1023) / 1024, 1024>>>(gridA, GRIDMAX, -1);
    k_init0<<<(n0 + 255) / 256, 256>>>(coors, n0, gridA, coordsA);
    k_set<<<1, 1>>>(counts, n0);

    const int S[7] = {128, 64, 32, 16, 8, 4, 2};
    const int M[7] = {100000, 100000, 32768, 4096, 512, 64, 8};
    const int CH[7][3] = {{3, 64, 64},    {64, 96, 96},   {96, 128, 128},
                          {128, 160, 160}, {160, 192, 192}, {192, 224, 224},
                          {224, 256, 256}};

    int* gc = gridA; int* gn = gridB;
    int* cc = coordsA; int* cn = coordsB;
    const float* cur = features;

    for (int L = 0; L < 7; L++) {
        int s = S[L], m = M[L];
        int Cin = CH[L][0], Cmid = CH[L][1], Cout = CH[L][2];

        k_pairs<<<(m + 255) / 256, 256>>>(cc, gc, counts + L, s, pairs);

        float* o1 = (cur == featsA) ? featsB : featsA;
        {
            dim3 g((m + BM - 1) / BM, (Cmid + BN - 1) / BN);
            k_conv_mma<<<g, 256>>>(cur, W[2 * L], pairs, counts + L, o1, Cin, Cmid);
        }
        float* o2 = (L == 6) ? dout : ((o1 == featsA) ? featsB : featsA);
        {
            dim3 g((m + BM - 1) / BM, (Cout + BN - 1) / BN);
            k_conv_mma<<<g, 256>>>(o1, W[2 * L + 1], pairs, counts + L, o2, Cmid, Cout);
        }

        if (L < 6) {
            int s2 = s / 2;
            int D2 = s2 * s2 * s2;
            int m2 = M[L + 1];
            k_fill<<<(D2 + 1023) / 1024, 1024>>>(flags, D2, 0);
            k_mark<<<(m + 255) / 256, 256>>>(cc, counts + L, s2, flags);
            int nB = (D2 + 1023) / 1024;
            k_scan_block<<<nB, 1024>>>(flags, ranks, bsums, D2);
            k_scan_sums<<<1, 1024>>>(bsums, nB);
            k_scan_add<<<nB, 1024>>>(ranks, flags, bsums, D2, counts + L + 1);
            k_build<<<(D2 + 255) / 256, 256>>>(flags, ranks, s2, gn, cn);

            float* po = (o2 == featsA) ? featsB : featsA;
            long tot = (long)m2 * Cout;
            k_pool<<<(int)((tot + 255) / 256), 256>>>(o2, po, gc, cn, counts + L + 1, s, Cout);
            cur = po;

            int* t = gc; gc = gn; gn = t;
            t = cc; cc = cn; cn = t;
        }
    }
}